// round 6
// baseline (speedup 1.0000x reference)
#include <cuda_runtime.h>
#include <cuda_fp16.h>

#define N_NODES 20000
#define N_EDGES 150000
#define FEAT 64
#define HEADS 8
#define NRBF 20
#define OUTD 512          // HEADS*FEAT
#define CUTOFF 5.0f
#define PI_F 3.14159265358979323846f

// Node-level Q/K projection tables in fp16.
__device__ __half g_Qh[(size_t)N_NODES * OUTD];
__device__ __half g_Kh[(size_t)N_NODES * OUTD];

typedef unsigned long long u64;

__device__ __forceinline__ u64 pack2(float lo, float hi) {
    u64 r; asm("mov.b64 %0, {%1, %2};" : "=l"(r) : "f"(lo), "f"(hi)); return r;
}
__device__ __forceinline__ void unpack2(u64 v, float& lo, float& hi) {
    asm("mov.b64 {%0, %1}, %2;" : "=f"(lo), "=f"(hi) : "l"(v));
}
// packed fp32x2 FMA: 2 fp32 MACs per issue slot
__device__ __forceinline__ u64 ffma2(u64 a, u64 b, u64 c) {
    u64 d; asm("fma.rn.f32x2 %0, %1, %2, %3;" : "=l"(d) : "l"(a), "l"(b), "l"(c)); return d;
}
__device__ __forceinline__ float silu_f(float x) {
    return __fdividef(x, 1.0f + __expf(-x));
}

// ============================================================================
// Kernel 1: node projections (unchanged — known passing, near fma-bound).
// ============================================================================
#define PM 128
#define PN 64

__device__ __forceinline__ int swzX(int row, int col) {
    return row * 64 + ((col + 4 * (row & 7)) & 63);
}
__device__ __forceinline__ int swzW(int row, int col) {
    return row * 64 + ((col + 4 * ((row >> 3) & 7)) & 63);
}

__global__ void __launch_bounds__(256, 2)
proj_kernel(const float* __restrict__ x,
            const float* __restrict__ Wq, const float* __restrict__ bq,
            const float* __restrict__ Wk, const float* __restrict__ bk)
{
    extern __shared__ float sm[];
    float* Xs = sm;             // [128][64] swizzled (X)
    float* Ws = sm + PM * 64;   // [64][64] swizzled (W)

    const float* W = blockIdx.z ? Wk : Wq;
    const float* b = blockIdx.z ? bk : bq;
    __half* out    = blockIdx.z ? g_Kh : g_Qh;

    const int t  = threadIdx.x;
    const int m0 = blockIdx.x * PM;
    const int n0 = blockIdx.y * PN;

    #pragma unroll
    for (int p = 0; p < 8; p++) {
        int idx = t + p * 256;
        int ml = idx >> 4, fs = (idx & 15) << 2;
        int node = m0 + ml;
        float4 v = make_float4(0.f, 0.f, 0.f, 0.f);
        if (node < N_NODES)
            v = *reinterpret_cast<const float4*>(x + (size_t)node * FEAT + fs);
        *reinterpret_cast<float4*>(Xs + swzX(ml, fs)) = v;
    }
    #pragma unroll
    for (int p = 0; p < 4; p++) {
        int idx = t + p * 256;
        int nl = idx >> 4, fs = (idx & 15) << 2;
        float4 v = *reinterpret_cast<const float4*>(W + (size_t)(n0 + nl) * FEAT + fs);
        *reinterpret_cast<float4*>(Ws + swzW(nl, fs)) = v;
    }
    __syncthreads();

    const int tx = t & 7;
    const int ty = t >> 3;

    float bn[8];
    #pragma unroll
    for (int j = 0; j < 8; j++) bn[j] = b[n0 + tx * 8 + j];

    u64 acc[4][8];
    #pragma unroll
    for (int i = 0; i < 4; i++)
        #pragma unroll
        for (int j = 0; j < 8; j++) acc[i][j] = 0ULL;

    #pragma unroll 4
    for (int fp = 0; fp < 32; fp++) {
        u64 x2[4], w2[8];
        #pragma unroll
        for (int i = 0; i < 4; i++)
            x2[i] = *reinterpret_cast<const u64*>(Xs + swzX(i * 32 + ty, 2 * fp));
        #pragma unroll
        for (int j = 0; j < 8; j++)
            w2[j] = *reinterpret_cast<const u64*>(Ws + swzW(tx * 8 + j, 2 * fp));
        #pragma unroll
        for (int i = 0; i < 4; i++)
            #pragma unroll
            for (int j = 0; j < 8; j++)
                acc[i][j] = ffma2(x2[i], w2[j], acc[i][j]);
    }

    #pragma unroll
    for (int i = 0; i < 4; i++) {
        int node = m0 + i * 32 + ty;
        if (node < N_NODES) {
            float v[8];
            #pragma unroll
            for (int j = 0; j < 8; j++) {
                float lo, hi; unpack2(acc[i][j], lo, hi);
                v[j] = lo + hi + bn[j];
            }
            __half2 h01 = __floats2half2_rn(v[0], v[1]);
            __half2 h23 = __floats2half2_rn(v[2], v[3]);
            __half2 h45 = __floats2half2_rn(v[4], v[5]);
            __half2 h67 = __floats2half2_rn(v[6], v[7]);
            __half* dst = out + (size_t)node * OUTD + n0 + tx * 8;
            *reinterpret_cast<uint2*>(dst)     = make_uint2(*(unsigned*)&h01, *(unsigned*)&h23);
            *reinterpret_cast<uint2*>(dst + 4) = make_uint2(*(unsigned*)&h45, *(unsigned*)&h67);
        }
    }
}

// ============================================================================
// Kernel 2: octet-cooperative edges.
// Warp = 4 octets x 8 lanes; octet g handles edges (base+g) and (base+4+g);
// lane o owns features f in [8o, 8o+8) of every head.
//  - q/k gathers: lane o reads the o-th 16B chunk of a 128B head-row ->
//    1 full line per (edge, head) -> 4 wavefronts per LDG.128 (was 32).
//  - W_dk in smem: row f in a 128B slot, chunk k at position (k + (f>>3))&7.
//    At each load step the 8 octet requests tile all 32 banks -> 1 phase.
//  - bias in per-octet table stride 68 floats -> conflict-free LDS.64.
//  - vector-halving shfl reduction: lane o ends with head o's sum.
// ============================================================================
#define EB 256
#define EDGES_PER_WARP 8
#define EDGES_PER_BLK  64   // 8 warps * 8 edges
#define ESMEM_FLOATS (OUTD * 32 + 8 * 68)   // 16384 + 544

__global__ void __launch_bounds__(EB, 2)
edge_kernel(const float* __restrict__ dist,
            const int* __restrict__ nbrs,
            const float* __restrict__ Wdk,
            const float* __restrict__ bdk,
            float* __restrict__ out)
{
    extern __shared__ float esm[];
    float* sW  = esm;                 // [512 rows][32 floats (128B slot)]
    float* sB2 = esm + OUTD * 32;     // [8 octets][68]

    const int t = threadIdx.x;

    // Fill sW with chunk rotation: chunk k of row f -> slot pos (k + (f>>3))&7
    for (int idx = t; idx < OUTD * 5; idx += EB) {
        int f = idx / 5, k = idx - f * 5;
        float4 v = *reinterpret_cast<const float4*>(Wdk + (size_t)f * NRBF + k * 4);
        int pos = (k + (f >> 3)) & 7;
        *reinterpret_cast<float4*>(sW + f * 32 + pos * 4) = v;
    }
    // Bias: sB2[o][h*8+j] = bdk[h*64 + 8o + j]
    for (int idx = t; idx < OUTD; idx += EB) {
        int o = idx >> 6, rem = idx & 63;      // rem = h*8 + j
        int h = rem >> 3, j = rem & 7;
        sB2[o * 68 + rem] = bdk[h * FEAT + o * 8 + j];
    }
    __syncthreads();

    const int lane = t & 31;
    const int o    = lane & 7;        // octet lane: feature chunk
    const int g    = lane >> 3;       // octet id: edge within warp
    const int warp = t >> 5;

    const int base = blockIdx.x * EDGES_PER_BLK + warp * EDGES_PER_WARP;
    const int eA = base + g;
    const int eB = base + 4 + g;
    const int eAc = (eA < N_EDGES) ? eA : (N_EDGES - 1);
    const int eBc = (eB < N_EDGES) ? eB : (N_EDGES - 1);

    const int2 nA = reinterpret_cast<const int2*>(nbrs)[eAc];
    const int2 nB = reinterpret_cast<const int2*>(nbrs)[eBc];
    const float dA = dist[eAc];
    const float dB = dist[eBc];

    // RBF via Chebyshev recurrence
    u64 ef2a[NRBF / 2], ef2b[NRBF / 2];
    {
        float s1, c1;
        __sincosf(dA * (PI_F / CUTOFF), &s1, &c1);
        const float eod = (dA < CUTOFF) ? __fdividef(0.5f * (c1 + 1.0f), dA) : 0.0f;
        const float c2 = 2.0f * c1;
        float p2 = 0.0f, p1 = s1;
        #pragma unroll
        for (int r = 0; r < NRBF / 2; r++) {
            float ea = p1 * eod;
            float sn = c2 * p1 - p2;  p2 = p1;  p1 = sn;
            float eb = p1 * eod;
            sn = c2 * p1 - p2;        p2 = p1;  p1 = sn;
            ef2a[r] = pack2(ea, eb);
        }
    }
    {
        float s1, c1;
        __sincosf(dB * (PI_F / CUTOFF), &s1, &c1);
        const float eod = (dB < CUTOFF) ? __fdividef(0.5f * (c1 + 1.0f), dB) : 0.0f;
        const float c2 = 2.0f * c1;
        float p2 = 0.0f, p1 = s1;
        #pragma unroll
        for (int r = 0; r < NRBF / 2; r++) {
            float ea = p1 * eod;
            float sn = c2 * p1 - p2;  p2 = p1;  p1 = sn;
            float eb = p1 * eod;
            sn = c2 * p1 - p2;        p2 = p1;  p1 = sn;
            ef2b[r] = pack2(ea, eb);
        }
    }

    const uint4* qA = reinterpret_cast<const uint4*>(g_Qh + (size_t)nA.x * OUTD);
    const uint4* kA = reinterpret_cast<const uint4*>(g_Kh + (size_t)nA.y * OUTD);
    const uint4* qB = reinterpret_cast<const uint4*>(g_Qh + (size_t)nB.x * OUTD);
    const uint4* kB = reinterpret_cast<const uint4*>(g_Kh + (size_t)nB.y * OUTD);

    float accA[HEADS], accB[HEADS];

    #pragma unroll 1
    for (int h = 0; h < HEADS; h++) {
        // gathers: 1 line per (edge, head, table)
        const uint4 qva = qA[h * 8 + o];
        const uint4 kva = kA[h * 8 + o];
        const uint4 qvb = qB[h * 8 + o];
        const uint4 kvb = kB[h * 8 + o];

        // per-row q*k products (8 per edge)
        float qkA[8], qkB[8];
        {
            const unsigned qa[4] = {qva.x, qva.y, qva.z, qva.w};
            const unsigned ka[4] = {kva.x, kva.y, kva.z, kva.w};
            const unsigned qb[4] = {qvb.x, qvb.y, qvb.z, qvb.w};
            const unsigned kb[4] = {kvb.x, kvb.y, kvb.z, kvb.w};
            #pragma unroll
            for (int m = 0; m < 4; m++) {
                float2 qf = __half22float2(*reinterpret_cast<const __half2*>(&qa[m]));
                float2 kf = __half22float2(*reinterpret_cast<const __half2*>(&ka[m]));
                qkA[2 * m]     = qf.x * kf.x;
                qkA[2 * m + 1] = qf.y * kf.y;
                qf = __half22float2(*reinterpret_cast<const __half2*>(&qb[m]));
                kf = __half22float2(*reinterpret_cast<const __half2*>(&kb[m]));
                qkB[2 * m]     = qf.x * kf.x;
                qkB[2 * m + 1] = qf.y * kf.y;
            }
        }

        // bias: 8 floats, conflict-free LDS.64
        float bb[8];
        {
            const u64* bp = reinterpret_cast<const u64*>(sB2 + o * 68 + h * 8);
            #pragma unroll
            for (int i = 0; i < 4; i++) {
                float lo, hi; unpack2(bp[i], lo, hi);
                bb[2 * i] = lo; bb[2 * i + 1] = hi;
            }
        }

        float pA = 0.0f, pB = 0.0f;
        const float* slot0 = sW + (h * FEAT + 8 * o) * 32;
        #pragma unroll
        for (int jj = 0; jj < 8; jj++) {
            const float* slot = slot0 + jj * 32;
            u64 zA = 0ULL, zB = 0ULL;
            #pragma unroll
            for (int k = 0; k < 5; k++) {
                const int pos = (k + o) & 7;
                const float4 w = *reinterpret_cast<const float4*>(slot + pos * 4);
                const u64 wlo = pack2(w.x, w.y);
                const u64 whi = pack2(w.z, w.w);
                zA = ffma2(ef2a[2 * k],     wlo, zA);
                zA = ffma2(ef2a[2 * k + 1], whi, zA);
                zB = ffma2(ef2b[2 * k],     wlo, zB);
                zB = ffma2(ef2b[2 * k + 1], whi, zB);
            }
            float lo, hi;
            unpack2(zA, lo, hi); const float dkA = silu_f(lo + hi + bb[jj]);
            unpack2(zB, lo, hi); const float dkB = silu_f(lo + hi + bb[jj]);
            pA = fmaf(qkA[jj], dkA, pA);
            pB = fmaf(qkB[jj], dkB, pB);
        }
        accA[h] = pA;
        accB[h] = pB;
    }

    // vector-halving exchange over the octet: lane o ends with head o's full sum
    #pragma unroll
    for (int i = 0; i < 4; i++) {
        float a = accA[i], b2 = accA[i + 4];
        float mine = (o & 4) ? b2 : a, send = (o & 4) ? a : b2;
        accA[i] = mine + __shfl_xor_sync(0xffffffffu, send, 4);
        a = accB[i]; b2 = accB[i + 4];
        mine = (o & 4) ? b2 : a; send = (o & 4) ? a : b2;
        accB[i] = mine + __shfl_xor_sync(0xffffffffu, send, 4);
    }
    #pragma unroll
    for (int i = 0; i < 2; i++) {
        float a = accA[i], b2 = accA[i + 2];
        float mine = (o & 2) ? b2 : a, send = (o & 2) ? a : b2;
        accA[i] = mine + __shfl_xor_sync(0xffffffffu, send, 2);
        a = accB[i]; b2 = accB[i + 2];
        mine = (o & 2) ? b2 : a; send = (o & 2) ? a : b2;
        accB[i] = mine + __shfl_xor_sync(0xffffffffu, send, 2);
    }
    {
        float a = accA[0], b2 = accA[1];
        float mine = (o & 1) ? b2 : a, send = (o & 1) ? a : b2;
        accA[0] = mine + __shfl_xor_sync(0xffffffffu, send, 1);
        a = accB[0]; b2 = accB[1];
        mine = (o & 1) ? b2 : a; send = (o & 1) ? a : b2;
        accB[0] = mine + __shfl_xor_sync(0xffffffffu, send, 1);
    }

    if (eA < N_EDGES) out[(size_t)eA * HEADS + o] = silu_f(accA[0]);
    if (eB < N_EDGES) out[(size_t)eB * HEADS + o] = silu_f(accB[0]);
}

// ============================================================================
extern "C" void kernel_launch(void* const* d_in, const int* in_sizes, int n_in,
                              void* d_out, int out_size)
{
    (void)in_sizes; (void)n_in; (void)out_size;
    const float* dist = (const float*)d_in[0];
    const int*   nbrs = (const int*)  d_in[1];
    const float* x_i  = (const float*)d_in[2];
    const float* W_q  = (const float*)d_in[3];
    const float* b_q  = (const float*)d_in[4];
    const float* W_k  = (const float*)d_in[5];
    const float* b_k  = (const float*)d_in[6];
    const float* W_dk = (const float*)d_in[7];
    const float* b_dk = (const float*)d_in[8];
    float* out = (float*)d_out;

    const int psmem = (PM * 64 + PN * 64) * (int)sizeof(float);  // 49152 B
    cudaFuncSetAttribute(proj_kernel, cudaFuncAttributeMaxDynamicSharedMemorySize, psmem);

    dim3 pg((N_NODES + PM - 1) / PM, OUTD / PN, 2);   // (157, 8, 2)
    proj_kernel<<<pg, 256, psmem>>>(x_i, W_q, b_q, W_k, b_k);

    const int esmem = ESMEM_FLOATS * (int)sizeof(float);         // 67712 B
    cudaFuncSetAttribute(edge_kernel, cudaFuncAttributeMaxDynamicSharedMemorySize, esmem);
    const int eblocks = (N_EDGES + EDGES_PER_BLK - 1) / EDGES_PER_BLK;  // 2344
    edge_kernel<<<eblocks, EB, esmem>>>(dist, nbrs, W_dk, b_dk, out);
}

// round 7
// speedup vs baseline: 1.5568x; 1.5568x over previous
#include <cuda_runtime.h>
#include <cuda_fp16.h>

#define N_NODES 20000
#define N_EDGES 150000
#define FEAT 64
#define HEADS 8
#define NRBF 20
#define OUTD 512          // HEADS*FEAT
#define CUTOFF 5.0f
#define PI_F 3.14159265358979323846f
#define GTAB 4096         // d_k lookup-table cells over d in [0.5, 5.0]

// Node-level Q/K projection tables in fp16.
__device__ __half g_Qh[(size_t)N_NODES * OUTD];
__device__ __half g_Kh[(size_t)N_NODES * OUTD];
// d_k(d) lookup table: row p = silu(W_dk . ef(d_p) + b), d_p = 0.5 + p*4.5/GTAB
__device__ __half g_dkT[(size_t)(GTAB + 1) * OUTD];

typedef unsigned long long u64;

__device__ __forceinline__ u64 pack2(float lo, float hi) {
    u64 r; asm("mov.b64 %0, {%1, %2};" : "=l"(r) : "f"(lo), "f"(hi)); return r;
}
__device__ __forceinline__ void unpack2(u64 v, float& lo, float& hi) {
    asm("mov.b64 {%0, %1}, %2;" : "=f"(lo), "=f"(hi) : "l"(v));
}
__device__ __forceinline__ u64 ffma2(u64 a, u64 b, u64 c) {
    u64 d; asm("fma.rn.f32x2 %0, %1, %2, %3;" : "=l"(d) : "l"(a), "l"(b), "l"(c)); return d;
}
__device__ __forceinline__ u64 mul2(u64 a, u64 b) {
    u64 d; asm("mul.rn.f32x2 %0, %1, %2;" : "=l"(d) : "l"(a), "l"(b)); return d;
}
__device__ __forceinline__ float silu_f(float x) {
    return __fdividef(x, 1.0f + __expf(-x));
}

// ============================================================================
// Kernel 1: node projections (unchanged — known passing).
// ============================================================================
#define PM 128
#define PN 64

__device__ __forceinline__ int swzX(int row, int col) {
    return row * 64 + ((col + 4 * (row & 7)) & 63);
}
__device__ __forceinline__ int swzW(int row, int col) {
    return row * 64 + ((col + 4 * ((row >> 3) & 7)) & 63);
}

__global__ void __launch_bounds__(256, 2)
proj_kernel(const float* __restrict__ x,
            const float* __restrict__ Wq, const float* __restrict__ bq,
            const float* __restrict__ Wk, const float* __restrict__ bk)
{
    extern __shared__ float sm[];
    float* Xs = sm;
    float* Ws = sm + PM * 64;

    const float* W = blockIdx.z ? Wk : Wq;
    const float* b = blockIdx.z ? bk : bq;
    __half* out    = blockIdx.z ? g_Kh : g_Qh;

    const int t  = threadIdx.x;
    const int m0 = blockIdx.x * PM;
    const int n0 = blockIdx.y * PN;

    #pragma unroll
    for (int p = 0; p < 8; p++) {
        int idx = t + p * 256;
        int ml = idx >> 4, fs = (idx & 15) << 2;
        int node = m0 + ml;
        float4 v = make_float4(0.f, 0.f, 0.f, 0.f);
        if (node < N_NODES)
            v = *reinterpret_cast<const float4*>(x + (size_t)node * FEAT + fs);
        *reinterpret_cast<float4*>(Xs + swzX(ml, fs)) = v;
    }
    #pragma unroll
    for (int p = 0; p < 4; p++) {
        int idx = t + p * 256;
        int nl = idx >> 4, fs = (idx & 15) << 2;
        float4 v = *reinterpret_cast<const float4*>(W + (size_t)(n0 + nl) * FEAT + fs);
        *reinterpret_cast<float4*>(Ws + swzW(nl, fs)) = v;
    }
    __syncthreads();

    const int tx = t & 7;
    const int ty = t >> 3;

    float bn[8];
    #pragma unroll
    for (int j = 0; j < 8; j++) bn[j] = b[n0 + tx * 8 + j];

    u64 acc[4][8];
    #pragma unroll
    for (int i = 0; i < 4; i++)
        #pragma unroll
        for (int j = 0; j < 8; j++) acc[i][j] = 0ULL;

    #pragma unroll 4
    for (int fp = 0; fp < 32; fp++) {
        u64 x2[4], w2[8];
        #pragma unroll
        for (int i = 0; i < 4; i++)
            x2[i] = *reinterpret_cast<const u64*>(Xs + swzX(i * 32 + ty, 2 * fp));
        #pragma unroll
        for (int j = 0; j < 8; j++)
            w2[j] = *reinterpret_cast<const u64*>(Ws + swzW(tx * 8 + j, 2 * fp));
        #pragma unroll
        for (int i = 0; i < 4; i++)
            #pragma unroll
            for (int j = 0; j < 8; j++)
                acc[i][j] = ffma2(x2[i], w2[j], acc[i][j]);
    }

    #pragma unroll
    for (int i = 0; i < 4; i++) {
        int node = m0 + i * 32 + ty;
        if (node < N_NODES) {
            float v[8];
            #pragma unroll
            for (int j = 0; j < 8; j++) {
                float lo, hi; unpack2(acc[i][j], lo, hi);
                v[j] = lo + hi + bn[j];
            }
            __half2 h01 = __floats2half2_rn(v[0], v[1]);
            __half2 h23 = __floats2half2_rn(v[2], v[3]);
            __half2 h45 = __floats2half2_rn(v[4], v[5]);
            __half2 h67 = __floats2half2_rn(v[6], v[7]);
            __half* dst = out + (size_t)node * OUTD + n0 + tx * 8;
            *reinterpret_cast<uint2*>(dst)     = make_uint2(*(unsigned*)&h01, *(unsigned*)&h23);
            *reinterpret_cast<uint2*>(dst + 4) = make_uint2(*(unsigned*)&h45, *(unsigned*)&h67);
        }
    }
}

// ============================================================================
// Kernel 2: build d_k table. Thread handles (grid point p, 8 head-strided dims
// c8 + 64j). W_dk staged in smem padded to 21 floats/row: compute-phase reads
// have lane-consecutive dims -> stride-21 addresses -> conflict-free.
// ============================================================================
#define TPAD 21

__global__ void __launch_bounds__(256)
table_kernel(const float* __restrict__ Wdk, const float* __restrict__ bdk)
{
    __shared__ float sW[OUTD * TPAD];   // 43008 B
    const int t = threadIdx.x;
    for (int i = t; i < OUTD * NRBF; i += 256) {
        int dim = i / NRBF, r = i - dim * NRBF;
        sW[dim * TPAD + r] = Wdk[i];
    }
    __syncthreads();

    const int tid = blockIdx.x * 256 + t;
    const int p   = tid >> 6;
    const int c8  = tid & 63;
    if (p > GTAB) return;

    const float d = 0.5f + (float)p * (4.5f / (float)GTAB);
    float ef[NRBF];
    {
        float s1, c1;
        __sincosf(d * (PI_F / CUTOFF), &s1, &c1);
        const float eod = __fdividef(0.5f * (c1 + 1.0f), d);
        const float c2 = 2.0f * c1;
        float p2 = 0.0f, p1 = s1;
        #pragma unroll
        for (int r = 0; r < NRBF; r++) {
            ef[r] = p1 * eod;
            float sn = c2 * p1 - p2;  p2 = p1;  p1 = sn;
        }
    }

    #pragma unroll
    for (int j = 0; j < 8; j++) {
        const int dim = j * 64 + c8;
        const float* wr = sW + dim * TPAD;
        float acc = bdk[dim];
        #pragma unroll
        for (int r = 0; r < NRBF; r++)
            acc = fmaf(ef[r], wr[r], acc);
        g_dkT[(size_t)p * OUTD + dim] = __float2half_rn(silu_f(acc));
    }
}

// ============================================================================
// Kernel 3: edges. Warp = 4 edges x 8 lanes; lane o reads 16B chunk o of each
// 128B line c (c = head). Per edge: q + k + dk0 + dk1 = 4 KB fp16 = 32 wf.
// d_k via fp32 lerp of table rows i0, i0+1. Octet shfl exchange -> lane o
// holds head o; coalesced 1-float stores (4 edges x 32B = one line per warp).
// ============================================================================
#define EB 256
#define EDGES_PER_BLK 32   // 8 warps * 4 edges

__global__ void __launch_bounds__(EB)
edge_kernel(const float* __restrict__ dist,
            const int* __restrict__ nbrs,
            float* __restrict__ out)
{
    const int t    = threadIdx.x;
    const int lane = t & 31;
    const int o    = lane & 7;
    const int g    = lane >> 3;
    const int warp = t >> 5;

    const int e  = blockIdx.x * EDGES_PER_BLK + warp * 4 + g;
    const int ec = (e < N_EDGES) ? e : (N_EDGES - 1);

    const int2 nb = reinterpret_cast<const int2*>(nbrs)[ec];
    const float d = dist[ec];

    float u = (d - 0.5f) * ((float)GTAB / 4.5f);
    u = fminf(fmaxf(u, 0.0f), (float)GTAB - 0.001f);
    const int i0 = (int)u;
    const float tf = u - (float)i0;
    const u64 t2 = pack2(tf, tf);
    const u64 s2 = pack2(1.0f - tf, 1.0f - tf);

    const uint4* qrow  = reinterpret_cast<const uint4*>(g_Qh  + (size_t)nb.x * OUTD);
    const uint4* krow  = reinterpret_cast<const uint4*>(g_Kh  + (size_t)nb.y * OUTD);
    const uint4* d0row = reinterpret_cast<const uint4*>(g_dkT + (size_t)i0  * OUTD);
    const uint4* d1row = d0row + (OUTD / 8);   // next grid row (64 uint4)

    float part[8];
    #pragma unroll 2
    for (int c = 0; c < 8; c++) {
        const int idx = c * 8 + o;
        const uint4 q4 = qrow[idx];
        const uint4 k4 = krow[idx];
        const uint4 a4 = d0row[idx];
        const uint4 b4 = d1row[idx];
        const unsigned qw[4] = {q4.x, q4.y, q4.z, q4.w};
        const unsigned kw[4] = {k4.x, k4.y, k4.z, k4.w};
        const unsigned aw[4] = {a4.x, a4.y, a4.z, a4.w};
        const unsigned bw[4] = {b4.x, b4.y, b4.z, b4.w};
        u64 acc = 0ULL;
        #pragma unroll
        for (int m = 0; m < 4; m++) {
            const float2 qf = __half22float2(*reinterpret_cast<const __half2*>(&qw[m]));
            const float2 kf = __half22float2(*reinterpret_cast<const __half2*>(&kw[m]));
            const float2 af = __half22float2(*reinterpret_cast<const __half2*>(&aw[m]));
            const float2 bf = __half22float2(*reinterpret_cast<const __half2*>(&bw[m]));
            const u64 qk = mul2(pack2(qf.x, qf.y), pack2(kf.x, kf.y));
            const u64 dk = ffma2(t2, pack2(bf.x, bf.y), mul2(s2, pack2(af.x, af.y)));
            acc = ffma2(qk, dk, acc);
        }
        float lo, hi; unpack2(acc, lo, hi);
        part[c] = lo + hi;
    }

    // octet vector-halving exchange: lane o ends with head o's full sum
    #pragma unroll
    for (int i = 0; i < 4; i++) {
        float a = part[i], b = part[i + 4];
        float mine = (o & 4) ? b : a, send = (o & 4) ? a : b;
        part[i] = mine + __shfl_xor_sync(0xffffffffu, send, 4);
    }
    #pragma unroll
    for (int i = 0; i < 2; i++) {
        float a = part[i], b = part[i + 2];
        float mine = (o & 2) ? b : a, send = (o & 2) ? a : b;
        part[i] = mine + __shfl_xor_sync(0xffffffffu, send, 2);
    }
    {
        float a = part[0], b = part[1];
        float mine = (o & 1) ? b : a, send = (o & 1) ? a : b;
        part[0] = mine + __shfl_xor_sync(0xffffffffu, send, 1);
    }

    if (e < N_EDGES)
        out[(size_t)e * HEADS + o] = silu_f(part[0]);
}

// ============================================================================
extern "C" void kernel_launch(void* const* d_in, const int* in_sizes, int n_in,
                              void* d_out, int out_size)
{
    (void)in_sizes; (void)n_in; (void)out_size;
    const float* dist = (const float*)d_in[0];
    const int*   nbrs = (const int*)  d_in[1];
    const float* x_i  = (const float*)d_in[2];
    const float* W_q  = (const float*)d_in[3];
    const float* b_q  = (const float*)d_in[4];
    const float* W_k  = (const float*)d_in[5];
    const float* b_k  = (const float*)d_in[6];
    const float* W_dk = (const float*)d_in[7];
    const float* b_dk = (const float*)d_in[8];
    float* out = (float*)d_out;

    const int psmem = (PM * 64 + PN * 64) * (int)sizeof(float);  // 49152 B
    cudaFuncSetAttribute(proj_kernel, cudaFuncAttributeMaxDynamicSharedMemorySize, psmem);

    dim3 pg((N_NODES + PM - 1) / PM, OUTD / PN, 2);   // (157, 8, 2)
    proj_kernel<<<pg, 256, psmem>>>(x_i, W_q, b_q, W_k, b_k);

    const int tthreads = (GTAB + 1) * 64;
    table_kernel<<<(tthreads + 255) / 256, 256>>>(W_dk, b_dk);

    const int eblocks = (N_EDGES + EDGES_PER_BLK - 1) / EDGES_PER_BLK;  // 4688
    edge_kernel<<<eblocks, EB>>>(dist, nbrs, out);
}

// round 8
// speedup vs baseline: 1.6556x; 1.0635x over previous
#include <cuda_runtime.h>
#include <cuda_fp16.h>

#define N_NODES 20000
#define N_EDGES 150000
#define FEAT 64
#define HEADS 8
#define NRBF 20
#define OUTD 512          // HEADS*FEAT
#define CUTOFF 5.0f
#define PI_F 3.14159265358979323846f
#define GTAB 4096         // d_k lookup-table cells over d in [0.5, 5.0]

// Node-level Q/K projection tables in fp16.
__device__ __half g_Qh[(size_t)N_NODES * OUTD];
__device__ __half g_Kh[(size_t)N_NODES * OUTD];
// d_k(d) lookup table: row p = silu(W_dk . ef(d_p) + b), d_p = 0.5 + p*4.5/GTAB
__device__ __half g_dkT[(size_t)(GTAB + 1) * OUTD];

typedef unsigned long long u64;

__device__ __forceinline__ u64 pack2(float lo, float hi) {
    u64 r; asm("mov.b64 %0, {%1, %2};" : "=l"(r) : "f"(lo), "f"(hi)); return r;
}
__device__ __forceinline__ void unpack2(u64 v, float& lo, float& hi) {
    asm("mov.b64 {%0, %1}, %2;" : "=f"(lo), "=f"(hi) : "l"(v));
}
__device__ __forceinline__ u64 ffma2(u64 a, u64 b, u64 c) {
    u64 d; asm("fma.rn.f32x2 %0, %1, %2, %3;" : "=l"(d) : "l"(a), "l"(b), "l"(c)); return d;
}
__device__ __forceinline__ u64 mul2(u64 a, u64 b) {
    u64 d; asm("mul.rn.f32x2 %0, %1, %2;" : "=l"(d) : "l"(a), "l"(b)); return d;
}
__device__ __forceinline__ float silu_f(float x) {
    return __fdividef(x, 1.0f + __expf(-x));
}

// ============================================================================
// Kernel 1: node projections, affine-address edition.
//  - warp w computes output cols n0 + w*8 + j  (j = 0..7, lane-invariant)
//    -> W reads are broadcast-32 LDS.64, affine: WsP[(w*8+j)*32 + fp]
//  - lane l computes rows m0 + l + 32*i (i = 0..3)
//    -> X reads at row-stride 1; XsP stride 33 u64 (264B) -> 2-way floor,
//       affine: XsP[(l+32*i)*33 + fp]
//  No swizzle, zero per-iteration address ALU.
// ============================================================================
#define PM 128
#define PN 64
#define XSTR 33                       // u64 stride per X row
#define PSM_U64 (PM * XSTR + PN * 32) // 4224 + 2048 u64 = 50176 B

__global__ void __launch_bounds__(256, 2)
proj_kernel(const float* __restrict__ x,
            const float* __restrict__ Wq, const float* __restrict__ bq,
            const float* __restrict__ Wk, const float* __restrict__ bk)
{
    extern __shared__ u64 smu[];
    u64* XsP = smu;                // [128][33] (row uses 32, 1 pad)
    u64* WsP = smu + PM * XSTR;    // [64][32]

    const float* W = blockIdx.z ? Wk : Wq;
    const float* b = blockIdx.z ? bk : bq;
    __half* out    = blockIdx.z ? g_Kh : g_Qh;

    const int t  = threadIdx.x;
    const int m0 = blockIdx.x * PM;
    const int n0 = blockIdx.y * PN;

    // ---- load X tile (128 x 64 floats) as 2x STS.64 per float4 ----
    #pragma unroll
    for (int p = 0; p < 8; p++) {
        int idx = t + p * 256;                 // 2048 float4s
        int ml = idx >> 4, fs = (idx & 15) << 2;
        int node = m0 + ml;
        float4 v = make_float4(0.f, 0.f, 0.f, 0.f);
        if (node < N_NODES)
            v = *reinterpret_cast<const float4*>(x + (size_t)node * FEAT + fs);
        u64* dst = XsP + ml * XSTR + (fs >> 1);
        dst[0] = pack2(v.x, v.y);
        dst[1] = pack2(v.z, v.w);
    }
    // ---- load W tile (64 x 64 floats), stride 32 u64 = 16B-aligned rows ----
    #pragma unroll
    for (int p = 0; p < 4; p++) {
        int idx = t + p * 256;                 // 1024 float4s
        int nl = idx >> 4, fs = (idx & 15) << 2;
        float4 v = *reinterpret_cast<const float4*>(W + (size_t)(n0 + nl) * FEAT + fs);
        *reinterpret_cast<float4*>(WsP + nl * 32 + (fs >> 1)) = v;
    }
    __syncthreads();

    const int lane = t & 31;
    const int w    = t >> 5;

    float bn[8];
    #pragma unroll
    for (int j = 0; j < 8; j++) bn[j] = b[n0 + w * 8 + j];

    const u64* xp = XsP + lane * XSTR;         // rows lane + 32i at +32i*XSTR
    const u64* wp = WsP + (w * 8) * 32;        // rows w*8+j at +32j

    u64 acc[4][8];
    #pragma unroll
    for (int i = 0; i < 4; i++)
        #pragma unroll
        for (int j = 0; j < 8; j++) acc[i][j] = 0ULL;

    #pragma unroll 4
    for (int fp = 0; fp < 32; fp++) {
        u64 x2[4], w2[8];
        #pragma unroll
        for (int i = 0; i < 4; i++)
            x2[i] = xp[i * 32 * XSTR + fp];
        #pragma unroll
        for (int j = 0; j < 8; j++)
            w2[j] = wp[j * 32 + fp];
        #pragma unroll
        for (int i = 0; i < 4; i++)
            #pragma unroll
            for (int j = 0; j < 8; j++)
                acc[i][j] = ffma2(x2[i], w2[j], acc[i][j]);
    }

    #pragma unroll
    for (int i = 0; i < 4; i++) {
        int node = m0 + i * 32 + lane;
        if (node < N_NODES) {
            float v[8];
            #pragma unroll
            for (int j = 0; j < 8; j++) {
                float lo, hi; unpack2(acc[i][j], lo, hi);
                v[j] = lo + hi + bn[j];
            }
            __half2 h01 = __floats2half2_rn(v[0], v[1]);
            __half2 h23 = __floats2half2_rn(v[2], v[3]);
            __half2 h45 = __floats2half2_rn(v[4], v[5]);
            __half2 h67 = __floats2half2_rn(v[6], v[7]);
            __half* dst = out + (size_t)node * OUTD + n0 + w * 8;
            *reinterpret_cast<uint2*>(dst)     = make_uint2(*(unsigned*)&h01, *(unsigned*)&h23);
            *reinterpret_cast<uint2*>(dst + 4) = make_uint2(*(unsigned*)&h45, *(unsigned*)&h67);
        }
    }
}

// ============================================================================
// Kernel 2: build d_k table (unchanged).
// ============================================================================
#define TPAD 21

__global__ void __launch_bounds__(256)
table_kernel(const float* __restrict__ Wdk, const float* __restrict__ bdk)
{
    __shared__ float sW[OUTD * TPAD];   // 43008 B
    const int t = threadIdx.x;
    for (int i = t; i < OUTD * NRBF; i += 256) {
        int dim = i / NRBF, r = i - dim * NRBF;
        sW[dim * TPAD + r] = Wdk[i];
    }
    __syncthreads();

    const int tid = blockIdx.x * 256 + t;
    const int p   = tid >> 6;
    const int c8  = tid & 63;
    if (p > GTAB) return;

    const float d = 0.5f + (float)p * (4.5f / (float)GTAB);
    float ef[NRBF];
    {
        float s1, c1;
        __sincosf(d * (PI_F / CUTOFF), &s1, &c1);
        const float eod = __fdividef(0.5f * (c1 + 1.0f), d);
        const float c2 = 2.0f * c1;
        float p2 = 0.0f, p1 = s1;
        #pragma unroll
        for (int r = 0; r < NRBF; r++) {
            ef[r] = p1 * eod;
            float sn = c2 * p1 - p2;  p2 = p1;  p1 = sn;
        }
    }

    #pragma unroll
    for (int j = 0; j < 8; j++) {
        const int dim = j * 64 + c8;
        const float* wr = sW + dim * TPAD;
        float acc = bdk[dim];
        #pragma unroll
        for (int r = 0; r < NRBF; r++)
            acc = fmaf(ef[r], wr[r], acc);
        g_dkT[(size_t)p * OUTD + dim] = __float2half_rn(silu_f(acc));
    }
}

// ============================================================================
// Kernel 3: edges (unchanged — octet-cooperative full-line gathers + lerp).
// ============================================================================
#define EB 256
#define EDGES_PER_BLK 32   // 8 warps * 4 edges

__global__ void __launch_bounds__(EB)
edge_kernel(const float* __restrict__ dist,
            const int* __restrict__ nbrs,
            float* __restrict__ out)
{
    const int t    = threadIdx.x;
    const int lane = t & 31;
    const int o    = lane & 7;
    const int g    = lane >> 3;
    const int warp = t >> 5;

    const int e  = blockIdx.x * EDGES_PER_BLK + warp * 4 + g;
    const int ec = (e < N_EDGES) ? e : (N_EDGES - 1);

    const int2 nb = reinterpret_cast<const int2*>(nbrs)[ec];
    const float d = dist[ec];

    float u = (d - 0.5f) * ((float)GTAB / 4.5f);
    u = fminf(fmaxf(u, 0.0f), (float)GTAB - 0.001f);
    const int i0 = (int)u;
    const float tf = u - (float)i0;
    const u64 t2 = pack2(tf, tf);
    const u64 s2 = pack2(1.0f - tf, 1.0f - tf);

    const uint4* qrow  = reinterpret_cast<const uint4*>(g_Qh  + (size_t)nb.x * OUTD);
    const uint4* krow  = reinterpret_cast<const uint4*>(g_Kh  + (size_t)nb.y * OUTD);
    const uint4* d0row = reinterpret_cast<const uint4*>(g_dkT + (size_t)i0  * OUTD);
    const uint4* d1row = d0row + (OUTD / 8);   // next grid row (64 uint4)

    float part[8];
    #pragma unroll 2
    for (int c = 0; c < 8; c++) {
        const int idx = c * 8 + o;
        const uint4 q4 = qrow[idx];
        const uint4 k4 = krow[idx];
        const uint4 a4 = d0row[idx];
        const uint4 b4 = d1row[idx];
        const unsigned qw[4] = {q4.x, q4.y, q4.z, q4.w};
        const unsigned kw[4] = {k4.x, k4.y, k4.z, k4.w};
        const unsigned aw[4] = {a4.x, a4.y, a4.z, a4.w};
        const unsigned bw[4] = {b4.x, b4.y, b4.z, b4.w};
        u64 acc = 0ULL;
        #pragma unroll
        for (int m = 0; m < 4; m++) {
            const float2 qf = __half22float2(*reinterpret_cast<const __half2*>(&qw[m]));
            const float2 kf = __half22float2(*reinterpret_cast<const __half2*>(&kw[m]));
            const float2 af = __half22float2(*reinterpret_cast<const __half2*>(&aw[m]));
            const float2 bf = __half22float2(*reinterpret_cast<const __half2*>(&bw[m]));
            const u64 qk = mul2(pack2(qf.x, qf.y), pack2(kf.x, kf.y));
            const u64 dk = ffma2(t2, pack2(bf.x, bf.y), mul2(s2, pack2(af.x, af.y)));
            acc = ffma2(qk, dk, acc);
        }
        float lo, hi; unpack2(acc, lo, hi);
        part[c] = lo + hi;
    }

    // octet vector-halving exchange: lane o ends with head o's full sum
    #pragma unroll
    for (int i = 0; i < 4; i++) {
        float a = part[i], b = part[i + 4];
        float mine = (o & 4) ? b : a, send = (o & 4) ? a : b;
        part[i] = mine + __shfl_xor_sync(0xffffffffu, send, 4);
    }
    #pragma unroll
    for (int i = 0; i < 2; i++) {
        float a = part[i], b = part[i + 2];
        float mine = (o & 2) ? b : a, send = (o & 2) ? a : b;
        part[i] = mine + __shfl_xor_sync(0xffffffffu, send, 2);
    }
    {
        float a = part[0], b = part[1];
        float mine = (o & 1) ? b : a, send = (o & 1) ? a : b;
        part[0] = mine + __shfl_xor_sync(0xffffffffu, send, 1);
    }

    if (e < N_EDGES)
        out[(size_t)e * HEADS + o] = silu_f(part[0]);
}

// ============================================================================
extern "C" void kernel_launch(void* const* d_in, const int* in_sizes, int n_in,
                              void* d_out, int out_size)
{
    (void)in_sizes; (void)n_in; (void)out_size;
    const float* dist = (const float*)d_in[0];
    const int*   nbrs = (const int*)  d_in[1];
    const float* x_i  = (const float*)d_in[2];
    const float* W_q  = (const float*)d_in[3];
    const float* b_q  = (const float*)d_in[4];
    const float* W_k  = (const float*)d_in[5];
    const float* b_k  = (const float*)d_in[6];
    const float* W_dk = (const float*)d_in[7];
    const float* b_dk = (const float*)d_in[8];
    float* out = (float*)d_out;

    const int psmem = PSM_U64 * (int)sizeof(u64);   // 50176 B
    cudaFuncSetAttribute(proj_kernel, cudaFuncAttributeMaxDynamicSharedMemorySize, psmem);

    dim3 pg((N_NODES + PM - 1) / PM, OUTD / PN, 2);   // (157, 8, 2)
    proj_kernel<<<pg, 256, psmem>>>(x_i, W_q, b_q, W_k, b_k);

    const int tthreads = (GTAB + 1) * 64;
    table_kernel<<<(tthreads + 255) / 256, 256>>>(W_dk, b_dk);

    const int eblocks = (N_EDGES + EDGES_PER_BLK - 1) / EDGES_PER_BLK;  // 4688
    edge_kernel<<<eblocks, EB>>>(dist, nbrs, out);
}

// round 9
// speedup vs baseline: 2.6729x; 1.6145x over previous
#include <cuda_runtime.h>
#include <cuda_fp16.h>
#include <cstdint>

#define N_NODES 20000
#define N_EDGES 150000
#define FEAT 64
#define HEADS 8
#define NRBF 20
#define OUTD 512          // HEADS*FEAT
#define CUTOFF 5.0f
#define PI_F 3.14159265358979323846f
#define GTAB 4096         // d_k lookup-table cells over d in [0.5, 5.0]

// Node-level Q/K projection tables in fp16.
__device__ __half g_Qh[(size_t)N_NODES * OUTD];
__device__ __half g_Kh[(size_t)N_NODES * OUTD];
// d_k(d) lookup table: row p = silu(W_dk . ef(d_p) + b), d_p = 0.5 + p*4.5/GTAB
__device__ __half g_dkT[(size_t)(GTAB + 1) * OUTD];

typedef unsigned long long u64;

__device__ __forceinline__ u64 pack2(float lo, float hi) {
    u64 r; asm("mov.b64 %0, {%1, %2};" : "=l"(r) : "f"(lo), "f"(hi)); return r;
}
__device__ __forceinline__ void unpack2(u64 v, float& lo, float& hi) {
    asm("mov.b64 {%0, %1}, %2;" : "=f"(lo), "=f"(hi) : "l"(v));
}
__device__ __forceinline__ u64 ffma2(u64 a, u64 b, u64 c) {
    u64 d; asm("fma.rn.f32x2 %0, %1, %2, %3;" : "=l"(d) : "l"(a), "l"(b), "l"(c)); return d;
}
__device__ __forceinline__ u64 mul2(u64 a, u64 b) {
    u64 d; asm("mul.rn.f32x2 %0, %1, %2;" : "=l"(d) : "l"(a), "l"(b)); return d;
}
__device__ __forceinline__ float silu_f(float x) {
    return __fdividef(x, 1.0f + __expf(-x));
}

__device__ __forceinline__ void ldsm4(uint32_t& r0, uint32_t& r1, uint32_t& r2, uint32_t& r3,
                                      uint32_t addr) {
    asm volatile("ldmatrix.sync.aligned.m8n8.x4.shared.b16 {%0,%1,%2,%3}, [%4];"
        : "=r"(r0), "=r"(r1), "=r"(r2), "=r"(r3) : "r"(addr));
}
__device__ __forceinline__ void mma16816(float& d0, float& d1, float& d2, float& d3,
                                         uint32_t a0, uint32_t a1, uint32_t a2, uint32_t a3,
                                         uint32_t b0, uint32_t b1) {
    asm volatile("mma.sync.aligned.m16n8k16.row.col.f32.f16.f16.f32 "
        "{%0,%1,%2,%3}, {%4,%5,%6,%7}, {%8,%9}, {%0,%1,%2,%3};"
        : "+f"(d0), "+f"(d1), "+f"(d2), "+f"(d3)
        : "r"(a0), "r"(a1), "r"(a2), "r"(a3), "r"(b0), "r"(b1));
}

// rows are 128 B (64 fp16); 16B-chunk XOR swizzle -> STS.128 and ldmatrix both bank-complete
__device__ __forceinline__ int swz128(int row, int kbyte) {
    return row * 128 + (kbyte ^ ((row & 7) << 4));
}

// ============================================================================
// Kernel 1: node projections on tensor cores.
// Block tile 128(M) x 128(N) x 64(K), 8 warps (4 on M, 2 on N), warp 32x64.
// A = x (fp32 -> fp16 staged), B = W rows (outputs) fp16; D fp32 + bias -> fp16.
// ============================================================================
#define PMT 128
#define PNT 128

__global__ void __launch_bounds__(256, 2)
proj_kernel(const float* __restrict__ x,
            const float* __restrict__ Wq, const float* __restrict__ bq,
            const float* __restrict__ Wk, const float* __restrict__ bk)
{
    __shared__ __half Ah[PMT * FEAT];   // 16 KB, swizzled
    __shared__ __half Bh[PNT * FEAT];   // 16 KB, swizzled

    const float* W = blockIdx.z ? Wk : Wq;
    const float* b = blockIdx.z ? bk : bq;
    __half* out    = blockIdx.z ? g_Kh : g_Qh;

    const int t  = threadIdx.x;
    const int m0 = blockIdx.x * PMT;
    const int n0 = blockIdx.y * PNT;

    const uint32_t aBase = (uint32_t)__cvta_generic_to_shared(Ah);
    const uint32_t bBase = (uint32_t)__cvta_generic_to_shared(Bh);

    // ---- stage A (x tile): 1024 16B-chunks, each = 8 floats -> 8 fp16 ----
    #pragma unroll
    for (int p = 0; p < 4; p++) {
        int idx = t + p * 256;
        int ml = idx >> 3, ch = idx & 7;
        int node = m0 + ml;
        float4 v0 = make_float4(0.f, 0.f, 0.f, 0.f), v1 = v0;
        if (node < N_NODES) {
            const float4* src = reinterpret_cast<const float4*>(x + (size_t)node * FEAT + ch * 8);
            v0 = src[0]; v1 = src[1];
        }
        __half2 h0 = __floats2half2_rn(v0.x, v0.y);
        __half2 h1 = __floats2half2_rn(v0.z, v0.w);
        __half2 h2 = __floats2half2_rn(v1.x, v1.y);
        __half2 h3 = __floats2half2_rn(v1.z, v1.w);
        *reinterpret_cast<uint4*>(reinterpret_cast<char*>(Ah) + swz128(ml, ch * 16)) =
            make_uint4(*(unsigned*)&h0, *(unsigned*)&h1, *(unsigned*)&h2, *(unsigned*)&h3);
    }
    // ---- stage B (W tile): rows = outputs n0+nl ----
    #pragma unroll
    for (int p = 0; p < 4; p++) {
        int idx = t + p * 256;
        int nl = idx >> 3, ch = idx & 7;
        const float4* src = reinterpret_cast<const float4*>(W + (size_t)(n0 + nl) * FEAT + ch * 8);
        float4 v0 = src[0], v1 = src[1];
        __half2 h0 = __floats2half2_rn(v0.x, v0.y);
        __half2 h1 = __floats2half2_rn(v0.z, v0.w);
        __half2 h2 = __floats2half2_rn(v1.x, v1.y);
        __half2 h3 = __floats2half2_rn(v1.z, v1.w);
        *reinterpret_cast<uint4*>(reinterpret_cast<char*>(Bh) + swz128(nl, ch * 16)) =
            make_uint4(*(unsigned*)&h0, *(unsigned*)&h1, *(unsigned*)&h2, *(unsigned*)&h3);
    }
    __syncthreads();

    const int lane = t & 31;
    const int warp = t >> 5;
    const int wm = warp & 3;     // M group: rows wm*32 .. +31
    const int wn = warp >> 2;    // N group: cols wn*64 .. +63
    const int r  = lane & 7;
    const int g  = lane >> 3;

    float d[2][8][4];
    #pragma unroll
    for (int mi = 0; mi < 2; mi++)
        #pragma unroll
        for (int nj = 0; nj < 8; nj++)
            #pragma unroll
            for (int q = 0; q < 4; q++) d[mi][nj][q] = 0.0f;

    #pragma unroll
    for (int kk = 0; kk < 4; kk++) {
        // A frags: a0=rows0-7 klow, a1=rows8-15 klow, a2=rows0-7 khigh, a3=rows8-15 khigh
        uint32_t a[2][4];
        #pragma unroll
        for (int mi = 0; mi < 2; mi++) {
            int row = wm * 32 + mi * 16 + ((g & 1) << 3) + r;
            int kb  = kk * 32 + ((g >> 1) << 4);
            ldsm4(a[mi][0], a[mi][1], a[mi][2], a[mi][3], aBase + swz128(row, kb));
        }
        // B frags: per np (pair of n8 tiles): r0=ntile even klow, r1=even khigh,
        //          r2=odd klow, r3=odd khigh
        uint32_t bf[4][4];
        #pragma unroll
        for (int np = 0; np < 4; np++) {
            int row = wn * 64 + np * 16 + ((g >> 1) << 3) + r;
            int kb  = kk * 32 + ((g & 1) << 4);
            ldsm4(bf[np][0], bf[np][1], bf[np][2], bf[np][3], bBase + swz128(row, kb));
        }
        #pragma unroll
        for (int mi = 0; mi < 2; mi++)
            #pragma unroll
            for (int np = 0; np < 4; np++) {
                mma16816(d[mi][2*np][0], d[mi][2*np][1], d[mi][2*np][2], d[mi][2*np][3],
                         a[mi][0], a[mi][1], a[mi][2], a[mi][3], bf[np][0], bf[np][1]);
                mma16816(d[mi][2*np+1][0], d[mi][2*np+1][1], d[mi][2*np+1][2], d[mi][2*np+1][3],
                         a[mi][0], a[mi][1], a[mi][2], a[mi][3], bf[np][2], bf[np][3]);
            }
    }

    // epilogue: bias + fp16 store. Lane covers cols (lane&3)*2,+1 of each n8 tile.
    float bn[8][2];
    #pragma unroll
    for (int nj = 0; nj < 8; nj++) {
        int col = n0 + wn * 64 + nj * 8 + (lane & 3) * 2;
        bn[nj][0] = b[col];
        bn[nj][1] = b[col + 1];
    }
    #pragma unroll
    for (int mi = 0; mi < 2; mi++) {
        int row0 = m0 + wm * 32 + mi * 16 + (lane >> 2);
        int row1 = row0 + 8;
        #pragma unroll
        for (int nj = 0; nj < 8; nj++) {
            int col = n0 + wn * 64 + nj * 8 + (lane & 3) * 2;
            if (row0 < N_NODES) {
                __half2 h = __floats2half2_rn(d[mi][nj][0] + bn[nj][0],
                                              d[mi][nj][1] + bn[nj][1]);
                *reinterpret_cast<__half2*>(out + (size_t)row0 * OUTD + col) = h;
            }
            if (row1 < N_NODES) {
                __half2 h = __floats2half2_rn(d[mi][nj][2] + bn[nj][0],
                                              d[mi][nj][3] + bn[nj][1]);
                *reinterpret_cast<__half2*>(out + (size_t)row1 * OUTD + col) = h;
            }
        }
    }
}

// ============================================================================
// Kernel 2: build d_k table (unchanged).
// ============================================================================
#define TPAD 21

__global__ void __launch_bounds__(256)
table_kernel(const float* __restrict__ Wdk, const float* __restrict__ bdk)
{
    __shared__ float sW[OUTD * TPAD];   // 43008 B
    const int t = threadIdx.x;
    for (int i = t; i < OUTD * NRBF; i += 256) {
        int dim = i / NRBF, r = i - dim * NRBF;
        sW[dim * TPAD + r] = Wdk[i];
    }
    __syncthreads();

    const int tid = blockIdx.x * 256 + t;
    const int p   = tid >> 6;
    const int c8  = tid & 63;
    if (p > GTAB) return;

    const float d = 0.5f + (float)p * (4.5f / (float)GTAB);
    float ef[NRBF];
    {
        float s1, c1;
        __sincosf(d * (PI_F / CUTOFF), &s1, &c1);
        const float eod = __fdividef(0.5f * (c1 + 1.0f), d);
        const float c2 = 2.0f * c1;
        float p2 = 0.0f, p1 = s1;
        #pragma unroll
        for (int r = 0; r < NRBF; r++) {
            ef[r] = p1 * eod;
            float sn = c2 * p1 - p2;  p2 = p1;  p1 = sn;
        }
    }

    #pragma unroll
    for (int j = 0; j < 8; j++) {
        const int dim = j * 64 + c8;
        const float* wr = sW + dim * TPAD;
        float acc = bdk[dim];
        #pragma unroll
        for (int r = 0; r < NRBF; r++)
            acc = fmaf(ef[r], wr[r], acc);
        g_dkT[(size_t)p * OUTD + dim] = __float2half_rn(silu_f(acc));
    }
}

// ============================================================================
// Kernel 3: edges (unchanged — octet-cooperative full-line gathers + lerp).
// ============================================================================
#define EB 256
#define EDGES_PER_BLK 32   // 8 warps * 4 edges

__global__ void __launch_bounds__(EB)
edge_kernel(const float* __restrict__ dist,
            const int* __restrict__ nbrs,
            float* __restrict__ out)
{
    const int t    = threadIdx.x;
    const int lane = t & 31;
    const int o    = lane & 7;
    const int g    = lane >> 3;
    const int warp = t >> 5;

    const int e  = blockIdx.x * EDGES_PER_BLK + warp * 4 + g;
    const int ec = (e < N_EDGES) ? e : (N_EDGES - 1);

    const int2 nb = reinterpret_cast<const int2*>(nbrs)[ec];
    const float d = dist[ec];

    float u = (d - 0.5f) * ((float)GTAB / 4.5f);
    u = fminf(fmaxf(u, 0.0f), (float)GTAB - 0.001f);
    const int i0 = (int)u;
    const float tf = u - (float)i0;
    const u64 t2 = pack2(tf, tf);
    const u64 s2 = pack2(1.0f - tf, 1.0f - tf);

    const uint4* qrow  = reinterpret_cast<const uint4*>(g_Qh  + (size_t)nb.x * OUTD);
    const uint4* krow  = reinterpret_cast<const uint4*>(g_Kh  + (size_t)nb.y * OUTD);
    const uint4* d0row = reinterpret_cast<const uint4*>(g_dkT + (size_t)i0  * OUTD);
    const uint4* d1row = d0row + (OUTD / 8);   // next grid row (64 uint4)

    float part[8];
    #pragma unroll 2
    for (int c = 0; c < 8; c++) {
        const int idx = c * 8 + o;
        const uint4 q4 = qrow[idx];
        const uint4 k4 = krow[idx];
        const uint4 a4 = d0row[idx];
        const uint4 b4 = d1row[idx];
        const unsigned qw[4] = {q4.x, q4.y, q4.z, q4.w};
        const unsigned kw[4] = {k4.x, k4.y, k4.z, k4.w};
        const unsigned aw[4] = {a4.x, a4.y, a4.z, a4.w};
        const unsigned bw[4] = {b4.x, b4.y, b4.z, b4.w};
        u64 acc = 0ULL;
        #pragma unroll
        for (int m = 0; m < 4; m++) {
            const float2 qf = __half22float2(*reinterpret_cast<const __half2*>(&qw[m]));
            const float2 kf = __half22float2(*reinterpret_cast<const __half2*>(&kw[m]));
            const float2 af = __half22float2(*reinterpret_cast<const __half2*>(&aw[m]));
            const float2 bf = __half22float2(*reinterpret_cast<const __half2*>(&bw[m]));
            const u64 qk = mul2(pack2(qf.x, qf.y), pack2(kf.x, kf.y));
            const u64 dk = ffma2(t2, pack2(bf.x, bf.y), mul2(s2, pack2(af.x, af.y)));
            acc = ffma2(qk, dk, acc);
        }
        float lo, hi; unpack2(acc, lo, hi);
        part[c] = lo + hi;
    }

    // octet vector-halving exchange: lane o ends with head o's full sum
    #pragma unroll
    for (int i = 0; i < 4; i++) {
        float a = part[i], b = part[i + 4];
        float mine = (o & 4) ? b : a, send = (o & 4) ? a : b;
        part[i] = mine + __shfl_xor_sync(0xffffffffu, send, 4);
    }
    #pragma unroll
    for (int i = 0; i < 2; i++) {
        float a = part[i], b = part[i + 2];
        float mine = (o & 2) ? b : a, send = (o & 2) ? a : b;
        part[i] = mine + __shfl_xor_sync(0xffffffffu, send, 2);
    }
    {
        float a = part[0], b = part[1];
        float mine = (o & 1) ? b : a, send = (o & 1) ? a : b;
        part[0] = mine + __shfl_xor_sync(0xffffffffu, send, 1);
    }

    if (e < N_EDGES)
        out[(size_t)e * HEADS + o] = silu_f(part[0]);
}

// ============================================================================
extern "C" void kernel_launch(void* const* d_in, const int* in_sizes, int n_in,
                              void* d_out, int out_size)
{
    (void)in_sizes; (void)n_in; (void)out_size;
    const float* dist = (const float*)d_in[0];
    const int*   nbrs = (const int*)  d_in[1];
    const float* x_i  = (const float*)d_in[2];
    const float* W_q  = (const float*)d_in[3];
    const float* b_q  = (const float*)d_in[4];
    const float* W_k  = (const float*)d_in[5];
    const float* b_k  = (const float*)d_in[6];
    const float* W_dk = (const float*)d_in[7];
    const float* b_dk = (const float*)d_in[8];
    float* out = (float*)d_out;

    dim3 pg((N_NODES + PMT - 1) / PMT, OUTD / PNT, 2);   // (157, 4, 2)
    proj_kernel<<<pg, 256>>>(x_i, W_q, b_q, W_k, b_k);

    const int tthreads = (GTAB + 1) * 64;
    table_kernel<<<(tthreads + 255) / 256, 256>>>(W_dk, b_dk);

    const int eblocks = (N_EDGES + EDGES_PER_BLK - 1) / EDGES_PER_BLK;  // 4688
    edge_kernel<<<eblocks, EB>>>(dist, nbrs, out);
}